// round 12
// baseline (speedup 1.0000x reference)
#include <cuda_runtime.h>
#include <cuda_fp16.h>
#include <cstdint>

#define NN     20000
#define FIN    50
#define HID    128
#define HEADS  4
#define FOUT   512            // HEADS*HID
#define E0     320000
#define ET     (E0 + NN)      // edges incl. self-loops = 340000
#define K1     64             // layer-1 K padded 50 -> 64
#define NB     20             // scan blocks (ceil(NN/1024))
#define RB     ((NN + 127) / 128)       // 157 row blocks
#define G1B    (4 * RB)                 // 628 GEMM blocks
#define DB     ((ET + 255) / 256)       // 1329 decode/scatter blocks

// ---------------- scratch (device globals; no allocation allowed) ----------
__device__ __half g_hA[(size_t)NN * FOUT];      // GEMM output (fp16 messages)
__device__ __half g_hB[(size_t)NN * FOUT];      // agg1 output (fp16)
__device__ __half g_x[(size_t)NN * K1];         // x fp16 (padded)
__device__ __half g_W1T[(size_t)FOUT * K1];     // W1^T fp16 [n][k]
__device__ __half g_W2T[(size_t)FOUT * FOUT];   // W2^T fp16 [n][k]
__device__ float g_asrc[NN * HEADS],  g_adst[NN * HEADS];    // layer-1 dots
__device__ float g_asrc2[NN * HEADS], g_adst2[NN * HEADS];   // layer-2 dots
__device__ float g_h3[NN], g_as3[NN], g_ad3[NN];
__device__ int   g_src[ET], g_dstv[ET], g_csrc[ET];
__device__ int   g_deg[NN], g_cursor[NN], g_rowoff[NN + 1];
__device__ int   g_bsum[32], g_boff[32];
__device__ int   g_ctr, g_flag;
__device__ int   g_is64;

// ---------------- helpers --------------------------------------------------
__device__ __forceinline__ float warp_red_sum(float v) {
    #pragma unroll
    for (int o = 16; o; o >>= 1) v += __shfl_xor_sync(0xffffffffu, v, o);
    return v;
}
__device__ __forceinline__ float warp_red_max(float v) {
    #pragma unroll
    for (int o = 16; o; o >>= 1) v = fmaxf(v, __shfl_xor_sync(0xffffffffu, v, o));
    return v;
}
__device__ __forceinline__ float leaky(float x) { return x > 0.f ? x : 0.2f * x; }

__device__ __forceinline__ uint32_t smem_u32(const void* p) {
    uint32_t a;
    asm("{ .reg .u64 t; cvta.to.shared.u64 t, %1; cvt.u32.u64 %0, t; }" : "=r"(a) : "l"(p));
    return a;
}

__device__ __forceinline__ void ldm_x4(unsigned r[4], uint32_t addr) {
    asm volatile("ldmatrix.sync.aligned.m8n8.x4.shared.b16 {%0,%1,%2,%3}, [%4];"
                 : "=r"(r[0]), "=r"(r[1]), "=r"(r[2]), "=r"(r[3]) : "r"(addr));
}
__device__ __forceinline__ void mma_f16(float c[4], const unsigned a[4],
                                        unsigned b0, unsigned b1) {
    asm volatile(
        "mma.sync.aligned.m16n8k16.row.col.f32.f16.f16.f32 "
        "{%0,%1,%2,%3}, {%4,%5,%6,%7}, {%8,%9}, {%0,%1,%2,%3};"
        : "+f"(c[0]), "+f"(c[1]), "+f"(c[2]), "+f"(c[3])
        : "r"(a[0]), "r"(a[1]), "r"(a[2]), "r"(a[3]), "r"(b0), "r"(b1));
}
__device__ __forceinline__ void cpa16(uint32_t dst, const void* src, bool p) {
    int sz = p ? 16 : 0;
    asm volatile("cp.async.cg.shared.global [%0], [%1], 16, %2;"
                 :: "r"(dst), "l"(src), "r"(sz));
}
__device__ __forceinline__ void cpa_commit() {
    asm volatile("cp.async.commit_group;");
}
template<int N> __device__ __forceinline__ void cpa_wait() {
    asm volatile("cp.async.wait_group %0;" :: "n"(N));
}

// ---------------- init: detect dtype + zero accumulators --------------------
__global__ void init_kernel(const unsigned* __restrict__ w) {
    int i = blockIdx.x * blockDim.x + threadIdx.x;
    if (i == 0) {
        int is64 = 1;
        for (int q = 1; q < 64; q += 2)
            if (w[q] != 0u) { is64 = 0; break; }
        g_is64 = is64;
        g_ctr = 0;
        g_flag = 0;
    }
    if (i < NN) g_deg[i] = 0;
    if (i < NN * HEADS) {
        g_asrc[i] = 0.f;  g_adst[i] = 0.f;
        g_asrc2[i] = 0.f; g_adst2[i] = 0.f;
    }
}

// ---------------- merged decode+count | W2 transpose | x fp16 | W1 ----------
__global__ __launch_bounds__(256) void decode_prep_kernel(
    const void* __restrict__ ei, const float* __restrict__ W1,
    const float* __restrict__ W2, const float* __restrict__ x)
{
    int b = blockIdx.x, t = threadIdx.x;
    if (b < DB) {
        int e = b * 256 + t;
        if (e >= ET) return;
        int s, d;
        if (e < E0) {
            if (g_is64) {
                const long long* p = (const long long*)ei;
                s = (int)p[e]; d = (int)p[E0 + e];
            } else {
                const int* p = (const int*)ei;
                s = p[e]; d = p[E0 + e];
            }
        } else {
            s = d = e - E0;
        }
        g_src[e] = s; g_dstv[e] = d;
        atomicAdd(&g_deg[d], 1);
    } else if (b < DB + 256) {
        __shared__ float tile[32][33];
        int bb = b - DB;
        int bx = (bb & 15) * 32, by = (bb >> 4) * 32;
        int tx = t & 31, ty = t >> 5;
        #pragma unroll
        for (int i = 0; i < 32; i += 8)
            tile[ty + i][tx] = W2[(size_t)(bx + ty + i) * 512 + by + tx];
        __syncthreads();
        #pragma unroll
        for (int i = 0; i < 32; i += 8) {
            float v = tile[tx][ty + i];
            g_W2T[(size_t)(by + ty + i) * 512 + bx + tx] = __float2half_rn(v);
        }
    } else if (b < DB + 256 + (NN * K1) / 256) {
        int idx = (b - DB - 256) * 256 + t;
        int n = idx >> 6, k = idx & 63;
        float v = (k < FIN) ? x[n * FIN + k] : 0.f;
        g_x[idx] = __float2half_rn(v);
    } else {
        int idx = (b - DB - 256 - (NN * K1) / 256) * 256 + t;
        if (idx < FOUT * K1) {
            int n = idx >> 6, k = idx & 63;
            float v = (k < FIN) ? W1[(size_t)k * 512 + n] : 0.f;
            g_W1T[idx] = __float2half_rn(v);
        }
    }
}

// ---------------- fused multi-block scan (one kernel, device flag sync) -----
__global__ __launch_bounds__(1024) void scan_kernel() {
    __shared__ int wsum[32];
    int b = blockIdx.x, t = threadIdx.x, lane = t & 31, w = t >> 5;
    int i = b * 1024 + t;
    int v = (i < NN) ? g_deg[i] : 0;
    int x = v;
    #pragma unroll
    for (int o = 1; o < 32; o <<= 1) {
        int y = __shfl_up_sync(0xffffffffu, x, o);
        if (lane >= o) x += y;
    }
    if (lane == 31) wsum[w] = x;
    __syncthreads();
    if (w == 0) {
        int y = wsum[lane];
        #pragma unroll
        for (int o = 1; o < 32; o <<= 1) {
            int z = __shfl_up_sync(0xffffffffu, y, o);
            if (lane >= o) y += z;
        }
        wsum[lane] = y;
    }
    __syncthreads();
    int incl = x + (w ? wsum[w - 1] : 0);
    int excl_local = incl - v;
    if (t == 1023) g_bsum[b] = incl;
    __threadfence();
    __syncthreads();

    if (t == 0) {
        int arrived = atomicAdd(&g_ctr, 1);
        if (arrived == NB - 1) {
            int acc = 0;
            #pragma unroll
            for (int q = 0; q < NB; q++) { g_boff[q] = acc; acc += g_bsum[q]; }
            __threadfence();
            atomicExch(&g_flag, 1);
        }
        while (atomicAdd(&g_flag, 0) == 0) {}
    }
    __syncthreads();

    int off = g_boff[b];
    if (i < NN) {
        g_rowoff[i + 1] = off + incl;
        g_cursor[i]     = off + excl_local;
    }
    if (b == 0 && t == 0) g_rowoff[0] = 0;
}

// ---------------- GEMM body: pure fp16 single-pass --------------------------
#define TB   10240                 // one tile array (128 rows x 80 B)
#define BUF  (2 * TB)              // one buffer = {A, B} = 20480
#define SM_ATT (2 * BUF)           // 40960
#define SM_TOTAL (SM_ATT + 1024)

template<int LAYER>
__device__ __forceinline__ void gemm_body(
    int head, int rowb, char* dsm,
    const float* __restrict__ atts, const float* __restrict__ attd)
{
    constexpr int K = (LAYER == 1) ? K1 : FOUT;
    constexpr int KITER = K / 32;

    float* satts = (float*)(dsm + SM_ATT);
    float* sattd = satts + 128;

    const __half* __restrict__ A = (LAYER == 1) ? g_x : g_hB;
    const __half* __restrict__ B = (LAYER == 1) ? g_W1T : g_W2T;

    int tid = threadIdx.x;
    int wid = tid >> 5, lane = tid & 31;
    int wm = (wid & 3) * 32;
    int wn = (wid >> 2) * 64;
    int rowBase = rowb * 128;
    int colBase = head * 128;
    uint32_t smb = smem_u32(dsm);

    if (tid < 128) {
        satts[tid] = atts[head * 128 + tid];
        sattd[tid] = attd[head * 128 + tid];
    }

    float c[2][8][4];
    #pragma unroll
    for (int t = 0; t < 2; t++)
        #pragma unroll
        for (int j = 0; j < 8; j++)
            #pragma unroll
            for (int q = 0; q < 4; q++) c[t][j][q] = 0.f;

    int r0l = tid >> 2, c8 = tid & 3;

    auto load_tile = [&](int it, int buf) {
        uint32_t bb = smb + buf * BUF;
        #pragma unroll
        for (int i = 0; i < 2; i++) {
            int r = r0l + i * 64;
            int sw = c8 ^ (r & 3);
            uint32_t ro = (uint32_t)r * 80u + (uint32_t)sw * 16u;
            int grow = rowBase + r;
            bool p = grow < NN;
            int gcl = p ? grow : (NN - 1);
            size_t goA = (size_t)gcl * K + it * 32 + c8 * 8;
            cpa16(bb + ro, A + goA, p);
            size_t goB = (size_t)(colBase + r) * K + it * 32 + c8 * 8;
            cpa16(bb + TB + ro, B + goB, true);
        }
    };

    load_tile(0, 0);
    cpa_commit();

    int lr = lane & 15, lhalf = lane >> 4;

    for (int it = 0; it < KITER; it++) {
        if (it + 1 < KITER) {
            load_tile(it + 1, (it + 1) & 1);
            cpa_commit();
            cpa_wait<1>();
        } else {
            cpa_wait<0>();
        }
        __syncthreads();

        uint32_t bb = smb + (it & 1) * BUF;
        uint32_t aBase = bb, bBase = bb + TB;

        #pragma unroll
        for (int s = 0; s < 2; s++) {
            unsigned af[2][4], bf[4][4];
            #pragma unroll
            for (int t = 0; t < 2; t++) {
                int row = wm + t * 16 + lr;
                uint32_t unit = (uint32_t)((s * 2 + lhalf) ^ (row & 3));
                uint32_t off = (uint32_t)row * 80u + unit * 16u;
                ldm_x4(af[t], aBase + off);
            }
            #pragma unroll
            for (int p = 0; p < 4; p++) {
                int row = wn + p * 16 + lr;
                uint32_t unit = (uint32_t)((s * 2 + lhalf) ^ (row & 3));
                uint32_t off = (uint32_t)row * 80u + unit * 16u;
                ldm_x4(bf[p], bBase + off);
            }
            #pragma unroll
            for (int t = 0; t < 2; t++) {
                #pragma unroll
                for (int j = 0; j < 8; j++) {
                    int p = j >> 1;
                    unsigned b0 = (j & 1) ? bf[p][1] : bf[p][0];
                    unsigned b1 = (j & 1) ? bf[p][3] : bf[p][2];
                    mma_f16(c[t][j], af[t], b0, b1);
                }
            }
        }
        __syncthreads();
    }

    float* asrc_out = (LAYER == 1) ? g_asrc : g_asrc2;
    float* adst_out = (LAYER == 1) ? g_adst : g_adst2;

    #pragma unroll
    for (int t = 0; t < 2; t++) {
        int r0 = rowBase + wm + t * 16 + (lane >> 2);
        #pragma unroll
        for (int j = 0; j < 8; j++) {
            int col = colBase + wn + j * 8 + (lane & 3) * 2;
            if (r0 < NN) {
                __half2 hv = __floats2half2_rn(c[t][j][0], c[t][j][1]);
                *(__half2*)&g_hA[(size_t)r0 * 512 + col] = hv;
            }
            if (r0 + 8 < NN) {
                __half2 hv = __floats2half2_rn(c[t][j][2], c[t][j][3]);
                *(__half2*)&g_hA[(size_t)(r0 + 8) * 512 + col] = hv;
            }
        }
        float s_a = 0.f, d_a = 0.f, s_b = 0.f, d_b = 0.f;
        #pragma unroll
        for (int j = 0; j < 8; j++) {
            int cl = wn + j * 8 + (lane & 3) * 2;
            float a0 = satts[cl], a1 = satts[cl + 1];
            float e0 = sattd[cl], e1 = sattd[cl + 1];
            s_a += c[t][j][0] * a0 + c[t][j][1] * a1;
            d_a += c[t][j][0] * e0 + c[t][j][1] * e1;
            s_b += c[t][j][2] * a0 + c[t][j][3] * a1;
            d_b += c[t][j][2] * e0 + c[t][j][3] * e1;
        }
        #pragma unroll
        for (int o = 1; o <= 2; o <<= 1) {
            s_a += __shfl_xor_sync(0xffffffffu, s_a, o);
            d_a += __shfl_xor_sync(0xffffffffu, d_a, o);
            s_b += __shfl_xor_sync(0xffffffffu, s_b, o);
            d_b += __shfl_xor_sync(0xffffffffu, d_b, o);
        }
        if ((lane & 3) == 0) {
            if (r0 < NN) {
                atomicAdd(&asrc_out[r0 * 4 + head], s_a);
                atomicAdd(&adst_out[r0 * 4 + head], d_a);
            }
            if (r0 + 8 < NN) {
                atomicAdd(&asrc_out[(r0 + 8) * 4 + head], s_b);
                atomicAdd(&adst_out[(r0 + 8) * 4 + head], d_b);
            }
        }
    }
}

// ---------------- GEMM1 + scatter merged (3 CTAs/SM target) -----------------
__global__ __launch_bounds__(256, 3) void gemm1_scatter_kernel(
    const float* __restrict__ as1, const float* __restrict__ ad1)
{
    if (blockIdx.x < G1B) {
        extern __shared__ char dsm[];
        gemm_body<1>(blockIdx.x & 3, blockIdx.x >> 2, dsm, as1, ad1);
    } else {
        int e = (blockIdx.x - G1B) * 256 + threadIdx.x;
        if (e < ET) {
            int d = g_dstv[e];
            int pos = atomicAdd(&g_cursor[d], 1);
            g_csrc[pos] = g_src[e];
        }
    }
}

// ---------------- GEMM2 standalone (3 CTAs/SM target) -----------------------
__global__ __launch_bounds__(256, 3) void gemm2_kernel(
    const float* __restrict__ as2, const float* __restrict__ ad2)
{
    extern __shared__ char dsm[];
    gemm_body<2>(blockIdx.x & 3, blockIdx.x >> 2, dsm, as2, ad2);
}

// ---------------- warp-per-node softmax + aggregate (fp16 gather) ----------
__device__ __forceinline__ void acc_edge(float4 acc[4], const float* wj,
                                         const uint2* __restrict__ hp) {
    #pragma unroll
    for (int i = 0; i < 4; i++) {
        float wgt = wj[i];
        uint2 u = hp[i * 32];
        float2 v01 = __half22float2(*(__half2*)&u.x);
        float2 v23 = __half22float2(*(__half2*)&u.y);
        acc[i].x = fmaf(wgt, v01.x, acc[i].x);
        acc[i].y = fmaf(wgt, v01.y, acc[i].y);
        acc[i].z = fmaf(wgt, v23.x, acc[i].z);
        acc[i].w = fmaf(wgt, v23.y, acc[i].w);
    }
}

template<int LAYER>
__global__ __launch_bounds__(256) void wagg_kernel(
    const float* __restrict__ bias, const float* __restrict__ W3,
    const float* __restrict__ as3p, const float* __restrict__ ad3p)
{
    __shared__ float lbuf[8][64 * 4];   // per warp: 64 edges x 4 heads
    __shared__ int   sbuf[8][64];       // per warp: src ids

    const float* __restrict__ asrc_in = (LAYER == 1) ? g_asrc : g_asrc2;
    const float* __restrict__ adst_in = (LAYER == 1) ? g_adst : g_adst2;

    int w = threadIdx.x >> 5, lane = threadIdx.x & 31;
    int n = blockIdx.x * 8 + w;
    if (n >= NN) return;
    int start = g_rowoff[n];
    int deg   = g_rowoff[n + 1] - start;
    int head  = lane & 3, eslot = lane >> 2;
    float ad = adst_in[n * 4 + head];

    float ssum;
    float4 acc[4];
    #pragma unroll
    for (int i = 0; i < 4; i++) acc[i] = make_float4(0.f, 0.f, 0.f, 0.f);

    if (deg <= 64) {
        float mx = -1e30f;
        for (int e = eslot; e < deg; e += 8) {
            int s = g_csrc[start + e];
            if (head == 0) sbuf[w][e] = s;
            float lg = leaky(asrc_in[s * 4 + head] + ad);
            lbuf[w][e * 4 + head] = lg;
            mx = fmaxf(mx, lg);
        }
        #pragma unroll
        for (int o = 4; o < 32; o <<= 1)
            mx = fmaxf(mx, __shfl_xor_sync(0xffffffffu, mx, o));
        float ls = 0.f;
        for (int e = eslot; e < deg; e += 8) {
            float wgt = __expf(lbuf[w][e * 4 + head] - mx);
            lbuf[w][e * 4 + head] = wgt;
            ls += wgt;
        }
        #pragma unroll
        for (int o = 4; o < 32; o <<= 1)
            ls += __shfl_xor_sync(0xffffffffu, ls, o);
        ssum = ls;
        __syncwarp();
        #pragma unroll 4
        for (int e2 = 0; e2 < deg; e2++) {
            const uint2* hp = (const uint2*)(g_hA + (size_t)sbuf[w][e2] * 512) + lane;
            acc_edge(acc, &lbuf[w][e2 * 4], hp);
        }
    } else {
        float mx = -1e30f;
        for (int c = 0; c < deg; c += 8) {
            int e = c + eslot;
            if (e < deg) {
                int s = g_csrc[start + e];
                mx = fmaxf(mx, leaky(asrc_in[s * 4 + head] + ad));
            }
        }
        #pragma unroll
        for (int o = 4; o < 32; o <<= 1)
            mx = fmaxf(mx, __shfl_xor_sync(0xffffffffu, mx, o));

        float ls = 0.f;
        for (int c = 0; c < deg; c += 32) {
            #pragma unroll
            for (int sp = 0; sp < 4; sp++) {
                int el = sp * 8 + eslot;
                int e = c + el;
                float wgt = 0.f;
                if (e < deg) {
                    int s = g_csrc[start + e];
                    if (head == 0) sbuf[w][el] = s;
                    wgt = __expf(leaky(asrc_in[s * 4 + head] + ad) - mx);
                }
                lbuf[w][el * 4 + head] = wgt;
                ls += wgt;
            }
            __syncwarp();
            int cend = min(32, deg - c);
            #pragma unroll 4
            for (int e2 = 0; e2 < cend; e2++) {
                const uint2* hp = (const uint2*)(g_hA + (size_t)sbuf[w][e2] * 512) + lane;
                acc_edge(acc, &lbuf[w][e2 * 4], hp);
            }
            __syncwarp();
        }
        #pragma unroll
        for (int o = 4; o < 32; o <<= 1)
            ls += __shfl_xor_sync(0xffffffffu, ls, o);
        ssum = ls;
    }

    float inv[4];
    #pragma unroll
    for (int i = 0; i < 4; i++)
        inv[i] = 1.f / (__shfl_sync(0xffffffffu, ssum, i) + 1e-16f);

    float p = 0.f;
    #pragma unroll
    for (int i = 0; i < 4; i++) {
        float4 b4 = ((const float4*)bias)[i * 32 + lane];
        float4 o;
        o.x = acc[i].x * inv[i] + b4.x;
        o.y = acc[i].y * inv[i] + b4.y;
        o.z = acc[i].z * inv[i] + b4.z;
        o.w = acc[i].w * inv[i] + b4.w;
        o.x = o.x > 0.f ? o.x : (__expf(o.x) - 1.f);
        o.y = o.y > 0.f ? o.y : (__expf(o.y) - 1.f);
        o.z = o.z > 0.f ? o.z : (__expf(o.z) - 1.f);
        o.w = o.w > 0.f ? o.w : (__expf(o.w) - 1.f);
        if (LAYER == 1) {
            __half2 h0 = __floats2half2_rn(o.x, o.y);
            __half2 h1 = __floats2half2_rn(o.z, o.w);
            size_t go = (size_t)n * 512 + i * 128 + lane * 4;
            *(uint2*)&g_hB[go] = make_uint2(*(unsigned*)&h0, *(unsigned*)&h1);
        } else {
            float4 w4 = ((const float4*)W3)[i * 32 + lane];
            p += o.x * w4.x + o.y * w4.y + o.z * w4.z + o.w * w4.w;
        }
    }
    if (LAYER == 2) {
        p = warp_red_sum(p);
        if (lane == 0) {
            g_h3[n] = p;
            g_as3[n] = p * as3p[0];
            g_ad3[n] = p * ad3p[0];
        }
    }
}

// ---------------- layer-3 aggregation ---------------------------------------
__global__ __launch_bounds__(256) void agg3_kernel(
    const float* __restrict__ b3, float* __restrict__ out)
{
    int n = blockIdx.x * 8 + (threadIdx.x >> 5);
    if (n >= NN) return;
    int lane = threadIdx.x & 31;
    int start = g_rowoff[n], deg = g_rowoff[n + 1] - start;
    float ad = g_ad3[n];
    float m = -1e30f;
    for (int e = lane; e < deg; e += 32) {
        int s = g_csrc[start + e];
        m = fmaxf(m, leaky(g_as3[s] + ad));
    }
    m = warp_red_max(m);
    float sum = 0.f, acc = 0.f;
    for (int e = lane; e < deg; e += 32) {
        int s = g_csrc[start + e];
        float w = __expf(leaky(g_as3[s] + ad) - m);
        sum += w;
        acc = fmaf(w, g_h3[s], acc);
    }
    sum = warp_red_sum(sum);
    acc = warp_red_sum(acc);
    if (!lane) out[n] = acc / (sum + 1e-16f) + b3[0];
}

// ---------------- launch ----------------------------------------------------
extern "C" void kernel_launch(void* const* d_in, const int* in_sizes, int n_in,
                              void* d_out, int out_size)
{
    const float* x   = (const float*)d_in[0];
    const void*  ei  = d_in[1];
    const float* W1  = (const float*)d_in[2];
    const float* as1 = (const float*)d_in[3];
    const float* ad1 = (const float*)d_in[4];
    const float* b1  = (const float*)d_in[5];
    const float* W2  = (const float*)d_in[6];
    const float* as2 = (const float*)d_in[7];
    const float* ad2 = (const float*)d_in[8];
    const float* b2  = (const float*)d_in[9];
    const float* W3  = (const float*)d_in[10];
    const float* as3 = (const float*)d_in[11];
    const float* ad3 = (const float*)d_in[12];
    const float* b3  = (const float*)d_in[13];
    float* out = (float*)d_out;

    cudaFuncSetAttribute(gemm1_scatter_kernel,
                         cudaFuncAttributeMaxDynamicSharedMemorySize, SM_TOTAL);
    cudaFuncSetAttribute(gemm2_kernel,
                         cudaFuncAttributeMaxDynamicSharedMemorySize, SM_TOTAL);

    int prep_blocks = DB + 256 + (NN * K1) / 256 + (FOUT * K1 + 255) / 256;

    // 0: init (dtype detect + zero + sync state)
    init_kernel<<<(NN * HEADS + 255) / 256, 256>>>((const unsigned*)ei);
    // 1: decode+count | weight/x prep
    decode_prep_kernel<<<prep_blocks, 256>>>(ei, W1, W2, x);
    // 2: fused degree scan
    scan_kernel<<<NB, 1024>>>();
    // 3: GEMM1 (+dots) overlapped with CSR scatter
    gemm1_scatter_kernel<<<G1B + DB, 256, SM_TOTAL>>>(as1, ad1);
    // 4: layer-1 softmax-aggregate
    wagg_kernel<1><<<(NN + 7) / 8, 256>>>(b1, W3, as3, ad3);
    // 5: GEMM2 (+dots)
    gemm2_kernel<<<G1B, 256, SM_TOTAL>>>(as2, ad2);
    // 6: layer-2 softmax-aggregate + fused W3 GEMV
    wagg_kernel<2><<<(NN + 7) / 8, 256>>>(b2, W3, as3, ad3);
    // 7: layer-3 scalar attention
    agg3_kernel<<<(NN + 7) / 8, 256>>>(b3, out);
}

// round 13
// speedup vs baseline: 1.1523x; 1.1523x over previous
#include <cuda_runtime.h>
#include <cuda_fp16.h>
#include <cstdint>

#define NN     20000
#define FIN    50
#define HID    128
#define HEADS  4
#define FOUT   512            // HEADS*HID
#define E0     320000
#define ET     (E0 + NN)      // edges incl. self-loops = 340000
#define K1     64             // layer-1 K padded 50 -> 64
#define NB     20             // scan blocks (ceil(NN/1024))
#define RB     ((NN + 127) / 128)       // 157 row blocks
#define G1B    (4 * RB)                 // 628 GEMM blocks
#define DB     ((ET + 255) / 256)       // 1329 decode/scatter blocks

// ---------------- scratch (device globals; no allocation allowed) ----------
__device__ __half g_hA[(size_t)NN * FOUT];      // GEMM output (fp16 messages)
__device__ __half g_hB[(size_t)NN * FOUT];      // agg1 output (fp16)
__device__ __half g_x[(size_t)NN * K1];         // x fp16 (padded)
__device__ __half g_W1T[(size_t)FOUT * K1];     // W1^T fp16 [n][k]
__device__ __half g_W2T[(size_t)FOUT * FOUT];   // W2^T fp16 [n][k]
__device__ float g_asrc[NN * HEADS],  g_adst[NN * HEADS];    // layer-1 dots
__device__ float g_asrc2[NN * HEADS], g_adst2[NN * HEADS];   // layer-2 dots
__device__ float g_h3[NN], g_as3[NN], g_ad3[NN];
__device__ int   g_src[ET], g_dstv[ET], g_csrc[ET];
__device__ int   g_deg[NN], g_cursor[NN], g_rowoff[NN + 1];
__device__ int   g_bsum[32], g_boff[32];
__device__ int   g_ctr, g_flag;
__device__ int   g_is64;

// ---------------- helpers --------------------------------------------------
__device__ __forceinline__ float warp_red_sum(float v) {
    #pragma unroll
    for (int o = 16; o; o >>= 1) v += __shfl_xor_sync(0xffffffffu, v, o);
    return v;
}
__device__ __forceinline__ float warp_red_max(float v) {
    #pragma unroll
    for (int o = 16; o; o >>= 1) v = fmaxf(v, __shfl_xor_sync(0xffffffffu, v, o));
    return v;
}
__device__ __forceinline__ float leaky(float x) { return x > 0.f ? x : 0.2f * x; }

__device__ __forceinline__ uint32_t smem_u32(const void* p) {
    uint32_t a;
    asm("{ .reg .u64 t; cvta.to.shared.u64 t, %1; cvt.u32.u64 %0, t; }" : "=r"(a) : "l"(p));
    return a;
}

__device__ __forceinline__ void ldm_x4(unsigned r[4], uint32_t addr) {
    asm volatile("ldmatrix.sync.aligned.m8n8.x4.shared.b16 {%0,%1,%2,%3}, [%4];"
                 : "=r"(r[0]), "=r"(r[1]), "=r"(r[2]), "=r"(r[3]) : "r"(addr));
}
__device__ __forceinline__ void mma_f16(float c[4], const unsigned a[4],
                                        unsigned b0, unsigned b1) {
    asm volatile(
        "mma.sync.aligned.m16n8k16.row.col.f32.f16.f16.f32 "
        "{%0,%1,%2,%3}, {%4,%5,%6,%7}, {%8,%9}, {%0,%1,%2,%3};"
        : "+f"(c[0]), "+f"(c[1]), "+f"(c[2]), "+f"(c[3])
        : "r"(a[0]), "r"(a[1]), "r"(a[2]), "r"(a[3]), "r"(b0), "r"(b1));
}
__device__ __forceinline__ void cpa16(uint32_t dst, const void* src, bool p) {
    int sz = p ? 16 : 0;
    asm volatile("cp.async.cg.shared.global [%0], [%1], 16, %2;"
                 :: "r"(dst), "l"(src), "r"(sz));
}
__device__ __forceinline__ void cpa_commit() {
    asm volatile("cp.async.commit_group;");
}
template<int N> __device__ __forceinline__ void cpa_wait() {
    asm volatile("cp.async.wait_group %0;" :: "n"(N));
}

// ---------------- init: detect dtype + zero accumulators --------------------
__global__ void init_kernel(const unsigned* __restrict__ w) {
    int i = blockIdx.x * blockDim.x + threadIdx.x;
    if (i == 0) {
        int is64 = 1;
        for (int q = 1; q < 64; q += 2)
            if (w[q] != 0u) { is64 = 0; break; }
        g_is64 = is64;
        g_ctr = 0;
        g_flag = 0;
    }
    if (i < NN) g_deg[i] = 0;
    if (i < NN * HEADS) {
        g_asrc[i] = 0.f;  g_adst[i] = 0.f;
        g_asrc2[i] = 0.f; g_adst2[i] = 0.f;
    }
}

// ---------------- merged decode+count | W2 transpose | x fp16 | W1 ----------
__global__ __launch_bounds__(256) void decode_prep_kernel(
    const void* __restrict__ ei, const float* __restrict__ W1,
    const float* __restrict__ W2, const float* __restrict__ x)
{
    int b = blockIdx.x, t = threadIdx.x;
    if (b < DB) {
        int e = b * 256 + t;
        if (e >= ET) return;
        int s, d;
        if (e < E0) {
            if (g_is64) {
                const long long* p = (const long long*)ei;
                s = (int)p[e]; d = (int)p[E0 + e];
            } else {
                const int* p = (const int*)ei;
                s = p[e]; d = p[E0 + e];
            }
        } else {
            s = d = e - E0;
        }
        g_src[e] = s; g_dstv[e] = d;
        atomicAdd(&g_deg[d], 1);
    } else if (b < DB + 256) {
        __shared__ float tile[32][33];
        int bb = b - DB;
        int bx = (bb & 15) * 32, by = (bb >> 4) * 32;
        int tx = t & 31, ty = t >> 5;
        #pragma unroll
        for (int i = 0; i < 32; i += 8)
            tile[ty + i][tx] = W2[(size_t)(bx + ty + i) * 512 + by + tx];
        __syncthreads();
        #pragma unroll
        for (int i = 0; i < 32; i += 8) {
            float v = tile[tx][ty + i];
            g_W2T[(size_t)(by + ty + i) * 512 + bx + tx] = __float2half_rn(v);
        }
    } else if (b < DB + 256 + (NN * K1) / 256) {
        int idx = (b - DB - 256) * 256 + t;
        int n = idx >> 6, k = idx & 63;
        float v = (k < FIN) ? x[n * FIN + k] : 0.f;
        g_x[idx] = __float2half_rn(v);
    } else {
        int idx = (b - DB - 256 - (NN * K1) / 256) * 256 + t;
        if (idx < FOUT * K1) {
            int n = idx >> 6, k = idx & 63;
            float v = (k < FIN) ? W1[(size_t)k * 512 + n] : 0.f;
            g_W1T[idx] = __float2half_rn(v);
        }
    }
}

// ---------------- fused multi-block scan (one kernel, device flag sync) -----
__global__ __launch_bounds__(1024) void scan_kernel() {
    __shared__ int wsum[32];
    int b = blockIdx.x, t = threadIdx.x, lane = t & 31, w = t >> 5;
    int i = b * 1024 + t;
    int v = (i < NN) ? g_deg[i] : 0;
    int x = v;
    #pragma unroll
    for (int o = 1; o < 32; o <<= 1) {
        int y = __shfl_up_sync(0xffffffffu, x, o);
        if (lane >= o) x += y;
    }
    if (lane == 31) wsum[w] = x;
    __syncthreads();
    if (w == 0) {
        int y = wsum[lane];
        #pragma unroll
        for (int o = 1; o < 32; o <<= 1) {
            int z = __shfl_up_sync(0xffffffffu, y, o);
            if (lane >= o) y += z;
        }
        wsum[lane] = y;
    }
    __syncthreads();
    int incl = x + (w ? wsum[w - 1] : 0);
    int excl_local = incl - v;
    if (t == 1023) g_bsum[b] = incl;
    __threadfence();
    __syncthreads();

    if (t == 0) {
        int arrived = atomicAdd(&g_ctr, 1);
        if (arrived == NB - 1) {
            int acc = 0;
            #pragma unroll
            for (int q = 0; q < NB; q++) { g_boff[q] = acc; acc += g_bsum[q]; }
            __threadfence();
            atomicExch(&g_flag, 1);
        }
        while (atomicAdd(&g_flag, 0) == 0) {}
    }
    __syncthreads();

    int off = g_boff[b];
    if (i < NN) {
        g_rowoff[i + 1] = off + incl;
        g_cursor[i]     = off + excl_local;
    }
    if (b == 0 && t == 0) g_rowoff[0] = 0;
}

// ---------------- GEMM body: pure fp16, 3-stage cp.async pipeline -----------
#define TB   10240                 // one tile array (128 rows x 80 B)
#define BUF  (2 * TB)              // one stage = {A, B} = 20480
#define NSTG 3
#define SM_ATT (NSTG * BUF)        // 61440
#define SM_TOTAL (SM_ATT + 1024)

template<int LAYER>
__device__ __forceinline__ void gemm_body(
    int head, int rowb, char* dsm,
    const float* __restrict__ atts, const float* __restrict__ attd)
{
    constexpr int K = (LAYER == 1) ? K1 : FOUT;
    constexpr int KITER = K / 32;

    float* satts = (float*)(dsm + SM_ATT);
    float* sattd = satts + 128;

    const __half* __restrict__ A = (LAYER == 1) ? g_x : g_hB;
    const __half* __restrict__ B = (LAYER == 1) ? g_W1T : g_W2T;

    int tid = threadIdx.x;
    int wid = tid >> 5, lane = tid & 31;
    int wm = (wid & 3) * 32;
    int wn = (wid >> 2) * 64;
    int rowBase = rowb * 128;
    int colBase = head * 128;
    uint32_t smb = smem_u32(dsm);

    if (tid < 128) {
        satts[tid] = atts[head * 128 + tid];
        sattd[tid] = attd[head * 128 + tid];
    }

    float c[2][8][4];
    #pragma unroll
    for (int t = 0; t < 2; t++)
        #pragma unroll
        for (int j = 0; j < 8; j++)
            #pragma unroll
            for (int q = 0; q < 4; q++) c[t][j][q] = 0.f;

    int r0l = tid >> 2, c8 = tid & 3;

    auto load_tile = [&](int it, int buf) {
        uint32_t bb = smb + buf * BUF;
        #pragma unroll
        for (int i = 0; i < 2; i++) {
            int r = r0l + i * 64;
            int sw = c8 ^ (r & 3);
            uint32_t ro = (uint32_t)r * 80u + (uint32_t)sw * 16u;
            int grow = rowBase + r;
            bool p = grow < NN;
            int gcl = p ? grow : (NN - 1);
            size_t goA = (size_t)gcl * K + it * 32 + c8 * 8;
            cpa16(bb + ro, A + goA, p);
            size_t goB = (size_t)(colBase + r) * K + it * 32 + c8 * 8;
            cpa16(bb + TB + ro, B + goB, true);
        }
    };

    // prologue: stages 0 and 1 in flight
    load_tile(0, 0);
    cpa_commit();
    if (KITER > 1) {
        load_tile(1, 1);
        cpa_commit();
    }

    int lr = lane & 15, lhalf = lane >> 4;

    for (int it = 0; it < KITER; it++) {
        // wait for tile `it`; then barrier (all warps done reading stage (it+2)%3
        // during compute(it-1)); then issue prefetch of it+2 into that stage.
        if (it + 1 < KITER) cpa_wait<1>();
        else                cpa_wait<0>();
        __syncthreads();
        if (it + 2 < KITER) {
            load_tile(it + 2, (it + 2) % NSTG);
            cpa_commit();
        }

        uint32_t bb = smb + (it % NSTG) * BUF;
        uint32_t aBase = bb, bBase = bb + TB;

        #pragma unroll
        for (int s = 0; s < 2; s++) {
            unsigned af[2][4], bf[4][4];
            #pragma unroll
            for (int t = 0; t < 2; t++) {
                int row = wm + t * 16 + lr;
                uint32_t unit = (uint32_t)((s * 2 + lhalf) ^ (row & 3));
                uint32_t off = (uint32_t)row * 80u + unit * 16u;
                ldm_x4(af[t], aBase + off);
            }
            #pragma unroll
            for (int p = 0; p < 4; p++) {
                int row = wn + p * 16 + lr;
                uint32_t unit = (uint32_t)((s * 2 + lhalf) ^ (row & 3));
                uint32_t off = (uint32_t)row * 80u + unit * 16u;
                ldm_x4(bf[p], bBase + off);
            }
            #pragma unroll
            for (int t = 0; t < 2; t++) {
                #pragma unroll
                for (int j = 0; j < 8; j++) {
                    int p = j >> 1;
                    unsigned b0 = (j & 1) ? bf[p][1] : bf[p][0];
                    unsigned b1 = (j & 1) ? bf[p][3] : bf[p][2];
                    mma_f16(c[t][j], af[t], b0, b1);
                }
            }
        }
    }

    float* asrc_out = (LAYER == 1) ? g_asrc : g_asrc2;
    float* adst_out = (LAYER == 1) ? g_adst : g_adst2;

    #pragma unroll
    for (int t = 0; t < 2; t++) {
        int r0 = rowBase + wm + t * 16 + (lane >> 2);
        #pragma unroll
        for (int j = 0; j < 8; j++) {
            int col = colBase + wn + j * 8 + (lane & 3) * 2;
            if (r0 < NN) {
                __half2 hv = __floats2half2_rn(c[t][j][0], c[t][j][1]);
                *(__half2*)&g_hA[(size_t)r0 * 512 + col] = hv;
            }
            if (r0 + 8 < NN) {
                __half2 hv = __floats2half2_rn(c[t][j][2], c[t][j][3]);
                *(__half2*)&g_hA[(size_t)(r0 + 8) * 512 + col] = hv;
            }
        }
        float s_a = 0.f, d_a = 0.f, s_b = 0.f, d_b = 0.f;
        #pragma unroll
        for (int j = 0; j < 8; j++) {
            int cl = wn + j * 8 + (lane & 3) * 2;
            float a0 = satts[cl], a1 = satts[cl + 1];
            float e0 = sattd[cl], e1 = sattd[cl + 1];
            s_a += c[t][j][0] * a0 + c[t][j][1] * a1;
            d_a += c[t][j][0] * e0 + c[t][j][1] * e1;
            s_b += c[t][j][2] * a0 + c[t][j][3] * a1;
            d_b += c[t][j][2] * e0 + c[t][j][3] * e1;
        }
        #pragma unroll
        for (int o = 1; o <= 2; o <<= 1) {
            s_a += __shfl_xor_sync(0xffffffffu, s_a, o);
            d_a += __shfl_xor_sync(0xffffffffu, d_a, o);
            s_b += __shfl_xor_sync(0xffffffffu, s_b, o);
            d_b += __shfl_xor_sync(0xffffffffu, d_b, o);
        }
        if ((lane & 3) == 0) {
            if (r0 < NN) {
                atomicAdd(&asrc_out[r0 * 4 + head], s_a);
                atomicAdd(&adst_out[r0 * 4 + head], d_a);
            }
            if (r0 + 8 < NN) {
                atomicAdd(&asrc_out[(r0 + 8) * 4 + head], s_b);
                atomicAdd(&adst_out[(r0 + 8) * 4 + head], d_b);
            }
        }
    }
}

// ---------------- GEMM1 + scatter merged ------------------------------------
__global__ __launch_bounds__(256) void gemm1_scatter_kernel(
    const float* __restrict__ as1, const float* __restrict__ ad1)
{
    if (blockIdx.x < G1B) {
        extern __shared__ char dsm[];
        gemm_body<1>(blockIdx.x & 3, blockIdx.x >> 2, dsm, as1, ad1);
    } else {
        int e = (blockIdx.x - G1B) * 256 + threadIdx.x;
        if (e < ET) {
            int d = g_dstv[e];
            int pos = atomicAdd(&g_cursor[d], 1);
            g_csrc[pos] = g_src[e];
        }
    }
}

// ---------------- GEMM2 standalone ------------------------------------------
__global__ __launch_bounds__(256) void gemm2_kernel(
    const float* __restrict__ as2, const float* __restrict__ ad2)
{
    extern __shared__ char dsm[];
    gemm_body<2>(blockIdx.x & 3, blockIdx.x >> 2, dsm, as2, ad2);
}

// ---------------- warp-per-node softmax + aggregate (fp16 gather) ----------
__device__ __forceinline__ void acc_edge(float4 acc[4], const float* wj,
                                         const uint2* __restrict__ hp) {
    #pragma unroll
    for (int i = 0; i < 4; i++) {
        float wgt = wj[i];
        uint2 u = hp[i * 32];
        float2 v01 = __half22float2(*(__half2*)&u.x);
        float2 v23 = __half22float2(*(__half2*)&u.y);
        acc[i].x = fmaf(wgt, v01.x, acc[i].x);
        acc[i].y = fmaf(wgt, v01.y, acc[i].y);
        acc[i].z = fmaf(wgt, v23.x, acc[i].z);
        acc[i].w = fmaf(wgt, v23.y, acc[i].w);
    }
}

template<int LAYER>
__global__ __launch_bounds__(256) void wagg_kernel(
    const float* __restrict__ bias, const float* __restrict__ W3,
    const float* __restrict__ as3p, const float* __restrict__ ad3p)
{
    __shared__ float lbuf[8][64 * 4];   // per warp: 64 edges x 4 heads
    __shared__ int   sbuf[8][64];       // per warp: src ids

    const float* __restrict__ asrc_in = (LAYER == 1) ? g_asrc : g_asrc2;
    const float* __restrict__ adst_in = (LAYER == 1) ? g_adst : g_adst2;

    int w = threadIdx.x >> 5, lane = threadIdx.x & 31;
    int n = blockIdx.x * 8 + w;
    if (n >= NN) return;
    int start = g_rowoff[n];
    int deg   = g_rowoff[n + 1] - start;
    int head  = lane & 3, eslot = lane >> 2;
    float ad = adst_in[n * 4 + head];

    float ssum;
    float4 acc[4];
    #pragma unroll
    for (int i = 0; i < 4; i++) acc[i] = make_float4(0.f, 0.f, 0.f, 0.f);

    if (deg <= 64) {
        float mx = -1e30f;
        for (int e = eslot; e < deg; e += 8) {
            int s = g_csrc[start + e];
            if (head == 0) sbuf[w][e] = s;
            float lg = leaky(asrc_in[s * 4 + head] + ad);
            lbuf[w][e * 4 + head] = lg;
            mx = fmaxf(mx, lg);
        }
        #pragma unroll
        for (int o = 4; o < 32; o <<= 1)
            mx = fmaxf(mx, __shfl_xor_sync(0xffffffffu, mx, o));
        float ls = 0.f;
        for (int e = eslot; e < deg; e += 8) {
            float wgt = __expf(lbuf[w][e * 4 + head] - mx);
            lbuf[w][e * 4 + head] = wgt;
            ls += wgt;
        }
        #pragma unroll
        for (int o = 4; o < 32; o <<= 1)
            ls += __shfl_xor_sync(0xffffffffu, ls, o);
        ssum = ls;
        __syncwarp();
        #pragma unroll 4
        for (int e2 = 0; e2 < deg; e2++) {
            const uint2* hp = (const uint2*)(g_hA + (size_t)sbuf[w][e2] * 512) + lane;
            acc_edge(acc, &lbuf[w][e2 * 4], hp);
        }
    } else {
        float mx = -1e30f;
        for (int c = 0; c < deg; c += 8) {
            int e = c + eslot;
            if (e < deg) {
                int s = g_csrc[start + e];
                mx = fmaxf(mx, leaky(asrc_in[s * 4 + head] + ad));
            }
        }
        #pragma unroll
        for (int o = 4; o < 32; o <<= 1)
            mx = fmaxf(mx, __shfl_xor_sync(0xffffffffu, mx, o));

        float ls = 0.f;
        for (int c = 0; c < deg; c += 32) {
            #pragma unroll
            for (int sp = 0; sp < 4; sp++) {
                int el = sp * 8 + eslot;
                int e = c + el;
                float wgt = 0.f;
                if (e < deg) {
                    int s = g_csrc[start + e];
                    if (head == 0) sbuf[w][el] = s;
                    wgt = __expf(leaky(asrc_in[s * 4 + head] + ad) - mx);
                }
                lbuf[w][el * 4 + head] = wgt;
                ls += wgt;
            }
            __syncwarp();
            int cend = min(32, deg - c);
            #pragma unroll 4
            for (int e2 = 0; e2 < cend; e2++) {
                const uint2* hp = (const uint2*)(g_hA + (size_t)sbuf[w][e2] * 512) + lane;
                acc_edge(acc, &lbuf[w][e2 * 4], hp);
            }
            __syncwarp();
        }
        #pragma unroll
        for (int o = 4; o < 32; o <<= 1)
            ls += __shfl_xor_sync(0xffffffffu, ls, o);
        ssum = ls;
    }

    float inv[4];
    #pragma unroll
    for (int i = 0; i < 4; i++)
        inv[i] = 1.f / (__shfl_sync(0xffffffffu, ssum, i) + 1e-16f);

    float p = 0.f;
    #pragma unroll
    for (int i = 0; i < 4; i++) {
        float4 b4 = ((const float4*)bias)[i * 32 + lane];
        float4 o;
        o.x = acc[i].x * inv[i] + b4.x;
        o.y = acc[i].y * inv[i] + b4.y;
        o.z = acc[i].z * inv[i] + b4.z;
        o.w = acc[i].w * inv[i] + b4.w;
        o.x = o.x > 0.f ? o.x : (__expf(o.x) - 1.f);
        o.y = o.y > 0.f ? o.y : (__expf(o.y) - 1.f);
        o.z = o.z > 0.f ? o.z : (__expf(o.z) - 1.f);
        o.w = o.w > 0.f ? o.w : (__expf(o.w) - 1.f);
        if (LAYER == 1) {
            __half2 h0 = __floats2half2_rn(o.x, o.y);
            __half2 h1 = __floats2half2_rn(o.z, o.w);
            size_t go = (size_t)n * 512 + i * 128 + lane * 4;
            *(uint2*)&g_hB[go] = make_uint2(*(unsigned*)&h0, *(unsigned*)&h1);
        } else {
            float4 w4 = ((const float4*)W3)[i * 32 + lane];
            p += o.x * w4.x + o.y * w4.y + o.z * w4.z + o.w * w4.w;
        }
    }
    if (LAYER == 2) {
        p = warp_red_sum(p);
        if (lane == 0) {
            g_h3[n] = p;
            g_as3[n] = p * as3p[0];
            g_ad3[n] = p * ad3p[0];
        }
    }
}

// ---------------- layer-3 aggregation ---------------------------------------
__global__ __launch_bounds__(256) void agg3_kernel(
    const float* __restrict__ b3, float* __restrict__ out)
{
    int n = blockIdx.x * 8 + (threadIdx.x >> 5);
    if (n >= NN) return;
    int lane = threadIdx.x & 31;
    int start = g_rowoff[n], deg = g_rowoff[n + 1] - start;
    float ad = g_ad3[n];
    float m = -1e30f;
    for (int e = lane; e < deg; e += 32) {
        int s = g_csrc[start + e];
        m = fmaxf(m, leaky(g_as3[s] + ad));
    }
    m = warp_red_max(m);
    float sum = 0.f, acc = 0.f;
    for (int e = lane; e < deg; e += 32) {
        int s = g_csrc[start + e];
        float w = __expf(leaky(g_as3[s] + ad) - m);
        sum += w;
        acc = fmaf(w, g_h3[s], acc);
    }
    sum = warp_red_sum(sum);
    acc = warp_red_sum(acc);
    if (!lane) out[n] = acc / (sum + 1e-16f) + b3[0];
}

// ---------------- launch ----------------------------------------------------
extern "C" void kernel_launch(void* const* d_in, const int* in_sizes, int n_in,
                              void* d_out, int out_size)
{
    const float* x   = (const float*)d_in[0];
    const void*  ei  = d_in[1];
    const float* W1  = (const float*)d_in[2];
    const float* as1 = (const float*)d_in[3];
    const float* ad1 = (const float*)d_in[4];
    const float* b1  = (const float*)d_in[5];
    const float* W2  = (const float*)d_in[6];
    const float* as2 = (const float*)d_in[7];
    const float* ad2 = (const float*)d_in[8];
    const float* b2  = (const float*)d_in[9];
    const float* W3  = (const float*)d_in[10];
    const float* as3 = (const float*)d_in[11];
    const float* ad3 = (const float*)d_in[12];
    const float* b3  = (const float*)d_in[13];
    float* out = (float*)d_out;

    cudaFuncSetAttribute(gemm1_scatter_kernel,
                         cudaFuncAttributeMaxDynamicSharedMemorySize, SM_TOTAL);
    cudaFuncSetAttribute(gemm2_kernel,
                         cudaFuncAttributeMaxDynamicSharedMemorySize, SM_TOTAL);

    int prep_blocks = DB + 256 + (NN * K1) / 256 + (FOUT * K1 + 255) / 256;

    // 0: init (dtype detect + zero + sync state)
    init_kernel<<<(NN * HEADS + 255) / 256, 256>>>((const unsigned*)ei);
    // 1: decode+count | weight/x prep
    decode_prep_kernel<<<prep_blocks, 256>>>(ei, W1, W2, x);
    // 2: fused degree scan
    scan_kernel<<<NB, 1024>>>();
    // 3: GEMM1 (+dots) overlapped with CSR scatter
    gemm1_scatter_kernel<<<G1B + DB, 256, SM_TOTAL>>>(as1, ad1);
    // 4: layer-1 softmax-aggregate
    wagg_kernel<1><<<(NN + 7) / 8, 256>>>(b1, W3, as3, ad3);
    // 5: GEMM2 (+dots)
    gemm2_kernel<<<G1B, 256, SM_TOTAL>>>(as2, ad2);
    // 6: layer-2 softmax-aggregate + fused W3 GEMV
    wagg_kernel<2><<<(NN + 7) / 8, 256>>>(b2, W3, as3, ad3);
    // 7: layer-3 scalar attention
    agg3_kernel<<<(NN + 7) / 8, 256>>>(b3, out);
}

// round 14
// speedup vs baseline: 1.4225x; 1.2345x over previous
#include <cuda_runtime.h>
#include <cuda_fp16.h>
#include <cstdint>

#define NN     20000
#define FIN    50
#define HID    128
#define HEADS  4
#define FOUT   512            // HEADS*HID
#define E0     320000
#define ET     (E0 + NN)      // edges incl. self-loops = 340000
#define K1     64             // layer-1 K padded 50 -> 64
#define NB     20             // scan blocks (ceil(NN/1024))
#define RB     ((NN + 127) / 128)       // 157 row blocks
#define G1B    (4 * RB)                 // 628 GEMM blocks
#define DB     ((ET + 255) / 256)       // 1329 decode/scatter blocks

// ---------------- scratch (device globals; no allocation allowed) ----------
__device__ __half g_hA[(size_t)NN * FOUT];      // GEMM output (fp16 messages)
__device__ __half g_hB[(size_t)NN * FOUT];      // agg1 output (fp16)
__device__ __half g_x[(size_t)NN * K1];         // x fp16 (padded)
__device__ __half g_W1T[(size_t)FOUT * K1];     // W1^T fp16 [n][k]
__device__ __half g_W2T[(size_t)FOUT * FOUT];   // W2^T fp16 [n][k]
__device__ float g_asrc[NN * HEADS],  g_adst[NN * HEADS];    // layer-1 dots
__device__ float g_asrc2[NN * HEADS], g_adst2[NN * HEADS];   // layer-2 dots
__device__ float g_h3[NN], g_as3[NN], g_ad3[NN];
__device__ int   g_src[ET], g_dstv[ET], g_csrc[ET];
__device__ int   g_deg[NN], g_cursor[NN], g_rowoff[NN + 1];
__device__ int   g_bsum[32], g_boff[32];
__device__ int   g_ctr, g_flag;
__device__ int   g_is64;

// ---------------- helpers --------------------------------------------------
__device__ __forceinline__ float warp_red_sum(float v) {
    #pragma unroll
    for (int o = 16; o; o >>= 1) v += __shfl_xor_sync(0xffffffffu, v, o);
    return v;
}
__device__ __forceinline__ float warp_red_max(float v) {
    #pragma unroll
    for (int o = 16; o; o >>= 1) v = fmaxf(v, __shfl_xor_sync(0xffffffffu, v, o));
    return v;
}
__device__ __forceinline__ float leaky(float x) { return x > 0.f ? x : 0.2f * x; }

__device__ __forceinline__ uint32_t smem_u32(const void* p) {
    uint32_t a;
    asm("{ .reg .u64 t; cvta.to.shared.u64 t, %1; cvt.u32.u64 %0, t; }" : "=r"(a) : "l"(p));
    return a;
}

__device__ __forceinline__ void ldm_x4(unsigned r[4], uint32_t addr) {
    asm volatile("ldmatrix.sync.aligned.m8n8.x4.shared.b16 {%0,%1,%2,%3}, [%4];"
                 : "=r"(r[0]), "=r"(r[1]), "=r"(r[2]), "=r"(r[3]) : "r"(addr));
}
__device__ __forceinline__ void mma_f16(float c[4], const unsigned a[4],
                                        unsigned b0, unsigned b1) {
    asm volatile(
        "mma.sync.aligned.m16n8k16.row.col.f32.f16.f16.f32 "
        "{%0,%1,%2,%3}, {%4,%5,%6,%7}, {%8,%9}, {%0,%1,%2,%3};"
        : "+f"(c[0]), "+f"(c[1]), "+f"(c[2]), "+f"(c[3])
        : "r"(a[0]), "r"(a[1]), "r"(a[2]), "r"(a[3]), "r"(b0), "r"(b1));
}
__device__ __forceinline__ void cpa16(uint32_t dst, const void* src, bool p) {
    int sz = p ? 16 : 0;
    asm volatile("cp.async.cg.shared.global [%0], [%1], 16, %2;"
                 :: "r"(dst), "l"(src), "r"(sz));
}
__device__ __forceinline__ void cpa_commit() {
    asm volatile("cp.async.commit_group;");
}
template<int N> __device__ __forceinline__ void cpa_wait() {
    asm volatile("cp.async.wait_group %0;" :: "n"(N));
}

// ---------------- init: detect dtype + zero accumulators --------------------
__global__ void init_kernel(const unsigned* __restrict__ w) {
    int i = blockIdx.x * blockDim.x + threadIdx.x;
    if (i == 0) {
        int is64 = 1;
        for (int q = 1; q < 64; q += 2)
            if (w[q] != 0u) { is64 = 0; break; }
        g_is64 = is64;
        g_ctr = 0;
        g_flag = 0;
    }
    if (i < NN) g_deg[i] = 0;
    if (i < NN * HEADS) {
        g_asrc[i] = 0.f;  g_adst[i] = 0.f;
        g_asrc2[i] = 0.f; g_adst2[i] = 0.f;
    }
}

// ---------------- merged decode+count | W2 transpose | x fp16 | W1 ----------
__global__ __launch_bounds__(256) void decode_prep_kernel(
    const void* __restrict__ ei, const float* __restrict__ W1,
    const float* __restrict__ W2, const float* __restrict__ x)
{
    int b = blockIdx.x, t = threadIdx.x;
    if (b < DB) {
        int e = b * 256 + t;
        if (e >= ET) return;
        int s, d;
        if (e < E0) {
            if (g_is64) {
                const long long* p = (const long long*)ei;
                s = (int)p[e]; d = (int)p[E0 + e];
            } else {
                const int* p = (const int*)ei;
                s = p[e]; d = p[E0 + e];
            }
        } else {
            s = d = e - E0;
        }
        g_src[e] = s; g_dstv[e] = d;
        atomicAdd(&g_deg[d], 1);
    } else if (b < DB + 256) {
        __shared__ float tile[32][33];
        int bb = b - DB;
        int bx = (bb & 15) * 32, by = (bb >> 4) * 32;
        int tx = t & 31, ty = t >> 5;
        #pragma unroll
        for (int i = 0; i < 32; i += 8)
            tile[ty + i][tx] = W2[(size_t)(bx + ty + i) * 512 + by + tx];
        __syncthreads();
        #pragma unroll
        for (int i = 0; i < 32; i += 8) {
            float v = tile[tx][ty + i];
            g_W2T[(size_t)(by + ty + i) * 512 + bx + tx] = __float2half_rn(v);
        }
    } else if (b < DB + 256 + (NN * K1) / 256) {
        int idx = (b - DB - 256) * 256 + t;
        int n = idx >> 6, k = idx & 63;
        float v = (k < FIN) ? x[n * FIN + k] : 0.f;
        g_x[idx] = __float2half_rn(v);
    } else {
        int idx = (b - DB - 256 - (NN * K1) / 256) * 256 + t;
        if (idx < FOUT * K1) {
            int n = idx >> 6, k = idx & 63;
            float v = (k < FIN) ? W1[(size_t)k * 512 + n] : 0.f;
            g_W1T[idx] = __float2half_rn(v);
        }
    }
}

// ---------------- fused multi-block scan (one kernel, device flag sync) -----
__global__ __launch_bounds__(1024) void scan_kernel() {
    __shared__ int wsum[32];
    int b = blockIdx.x, t = threadIdx.x, lane = t & 31, w = t >> 5;
    int i = b * 1024 + t;
    int v = (i < NN) ? g_deg[i] : 0;
    int x = v;
    #pragma unroll
    for (int o = 1; o < 32; o <<= 1) {
        int y = __shfl_up_sync(0xffffffffu, x, o);
        if (lane >= o) x += y;
    }
    if (lane == 31) wsum[w] = x;
    __syncthreads();
    if (w == 0) {
        int y = wsum[lane];
        #pragma unroll
        for (int o = 1; o < 32; o <<= 1) {
            int z = __shfl_up_sync(0xffffffffu, y, o);
            if (lane >= o) y += z;
        }
        wsum[lane] = y;
    }
    __syncthreads();
    int incl = x + (w ? wsum[w - 1] : 0);
    int excl_local = incl - v;
    if (t == 1023) g_bsum[b] = incl;
    __threadfence();
    __syncthreads();

    if (t == 0) {
        int arrived = atomicAdd(&g_ctr, 1);
        if (arrived == NB - 1) {
            int acc = 0;
            #pragma unroll
            for (int q = 0; q < NB; q++) { g_boff[q] = acc; acc += g_bsum[q]; }
            __threadfence();
            atomicExch(&g_flag, 1);
        }
        while (atomicAdd(&g_flag, 0) == 0) {}
    }
    __syncthreads();

    int off = g_boff[b];
    if (i < NN) {
        g_rowoff[i + 1] = off + incl;
        g_cursor[i]     = off + excl_local;
    }
    if (b == 0 && t == 0) g_rowoff[0] = 0;
}

// ---------------- GEMM body: fp16, 64-wide K stages, 3-stage pipeline -------
#define TBH  16384                 // one tile array: 128 rows x 128 B
#define BUF  (2 * TBH)             // one stage = {A, B} = 32768
#define NSTG 3
#define SM_ATT (NSTG * BUF)        // 98304
#define SM_TOTAL (SM_ATT + 1024)

template<int LAYER>
__device__ __forceinline__ void gemm_body(
    int head, int rowb, char* dsm,
    const float* __restrict__ atts, const float* __restrict__ attd)
{
    constexpr int K = (LAYER == 1) ? K1 : FOUT;
    constexpr int KOUT = K / 64;

    float* satts = (float*)(dsm + SM_ATT);
    float* sattd = satts + 128;

    const __half* __restrict__ A = (LAYER == 1) ? g_x : g_hB;
    const __half* __restrict__ B = (LAYER == 1) ? g_W1T : g_W2T;

    int tid = threadIdx.x;
    int wid = tid >> 5, lane = tid & 31;
    int wm = (wid & 3) * 32;
    int wn = (wid >> 2) * 64;
    int rowBase = rowb * 128;
    int colBase = head * 128;
    uint32_t smb = smem_u32(dsm);

    if (tid < 128) {
        satts[tid] = atts[head * 128 + tid];
        sattd[tid] = attd[head * 128 + tid];
    }

    float c[2][8][4];
    #pragma unroll
    for (int t = 0; t < 2; t++)
        #pragma unroll
        for (int j = 0; j < 8; j++)
            #pragma unroll
            for (int q = 0; q < 4; q++) c[t][j][q] = 0.f;

    auto load_tile = [&](int oc, int buf) {
        uint32_t bb = smb + buf * BUF;
        #pragma unroll
        for (int i = 0; i < 4; i++) {
            int idx = tid + i * 256;           // 0..1023 units
            int r = idx >> 3, c8 = idx & 7;
            int sw = c8 ^ (r & 7);
            uint32_t ro = (uint32_t)r * 128u + (uint32_t)sw * 16u;
            int grow = rowBase + r;
            bool p = grow < NN;
            int gcl = p ? grow : (NN - 1);
            size_t goA = (size_t)gcl * K + oc * 64 + c8 * 8;
            cpa16(bb + ro, A + goA, p);
            size_t goB = (size_t)(colBase + r) * K + oc * 64 + c8 * 8;
            cpa16(bb + TBH + ro, B + goB, true);
        }
    };

    // prologue
    load_tile(0, 0);
    cpa_commit();
    if (KOUT > 1) {
        load_tile(1, 1);
        cpa_commit();
    }

    int lr = lane & 15, lhalf = lane >> 4;

    for (int oc = 0; oc < KOUT; oc++) {
        if (oc + 1 < KOUT) cpa_wait<1>();
        else               cpa_wait<0>();
        __syncthreads();
        if (oc + 2 < KOUT) {
            load_tile(oc + 2, (oc + 2) % NSTG);
            cpa_commit();
        }

        uint32_t bb = smb + (oc % NSTG) * BUF;
        uint32_t aBase = bb, bBase = bb + TBH;

        #pragma unroll
        for (int s = 0; s < 4; s++) {
            unsigned af[2][4], bf[4][4];
            #pragma unroll
            for (int t = 0; t < 2; t++) {
                int row = wm + t * 16 + lr;
                uint32_t unit = (uint32_t)((s * 2 + lhalf) ^ (row & 7));
                uint32_t off = (uint32_t)row * 128u + unit * 16u;
                ldm_x4(af[t], aBase + off);
            }
            #pragma unroll
            for (int p = 0; p < 4; p++) {
                int row = wn + p * 16 + lr;
                uint32_t unit = (uint32_t)((s * 2 + lhalf) ^ (row & 7));
                uint32_t off = (uint32_t)row * 128u + unit * 16u;
                ldm_x4(bf[p], bBase + off);
            }
            #pragma unroll
            for (int t = 0; t < 2; t++) {
                #pragma unroll
                for (int j = 0; j < 8; j++) {
                    int p = j >> 1;
                    unsigned b0 = (j & 1) ? bf[p][1] : bf[p][0];
                    unsigned b1 = (j & 1) ? bf[p][3] : bf[p][2];
                    mma_f16(c[t][j], af[t], b0, b1);
                }
            }
        }
    }

    float* asrc_out = (LAYER == 1) ? g_asrc : g_asrc2;
    float* adst_out = (LAYER == 1) ? g_adst : g_adst2;

    #pragma unroll
    for (int t = 0; t < 2; t++) {
        int r0 = rowBase + wm + t * 16 + (lane >> 2);
        #pragma unroll
        for (int j = 0; j < 8; j++) {
            int col = colBase + wn + j * 8 + (lane & 3) * 2;
            if (r0 < NN) {
                __half2 hv = __floats2half2_rn(c[t][j][0], c[t][j][1]);
                *(__half2*)&g_hA[(size_t)r0 * 512 + col] = hv;
            }
            if (r0 + 8 < NN) {
                __half2 hv = __floats2half2_rn(c[t][j][2], c[t][j][3]);
                *(__half2*)&g_hA[(size_t)(r0 + 8) * 512 + col] = hv;
            }
        }
        float s_a = 0.f, d_a = 0.f, s_b = 0.f, d_b = 0.f;
        #pragma unroll
        for (int j = 0; j < 8; j++) {
            int cl = wn + j * 8 + (lane & 3) * 2;
            float a0 = satts[cl], a1 = satts[cl + 1];
            float e0 = sattd[cl], e1 = sattd[cl + 1];
            s_a += c[t][j][0] * a0 + c[t][j][1] * a1;
            d_a += c[t][j][0] * e0 + c[t][j][1] * e1;
            s_b += c[t][j][2] * a0 + c[t][j][3] * a1;
            d_b += c[t][j][2] * e0 + c[t][j][3] * e1;
        }
        #pragma unroll
        for (int o = 1; o <= 2; o <<= 1) {
            s_a += __shfl_xor_sync(0xffffffffu, s_a, o);
            d_a += __shfl_xor_sync(0xffffffffu, d_a, o);
            s_b += __shfl_xor_sync(0xffffffffu, s_b, o);
            d_b += __shfl_xor_sync(0xffffffffu, d_b, o);
        }
        if ((lane & 3) == 0) {
            if (r0 < NN) {
                atomicAdd(&asrc_out[r0 * 4 + head], s_a);
                atomicAdd(&adst_out[r0 * 4 + head], d_a);
            }
            if (r0 + 8 < NN) {
                atomicAdd(&asrc_out[(r0 + 8) * 4 + head], s_b);
                atomicAdd(&adst_out[(r0 + 8) * 4 + head], d_b);
            }
        }
    }
}

// ---------------- GEMM1 + scatter merged ------------------------------------
__global__ __launch_bounds__(256) void gemm1_scatter_kernel(
    const float* __restrict__ as1, const float* __restrict__ ad1)
{
    if (blockIdx.x < G1B) {
        extern __shared__ char dsm[];
        gemm_body<1>(blockIdx.x & 3, blockIdx.x >> 2, dsm, as1, ad1);
    } else {
        int e = (blockIdx.x - G1B) * 256 + threadIdx.x;
        if (e < ET) {
            int d = g_dstv[e];
            int pos = atomicAdd(&g_cursor[d], 1);
            g_csrc[pos] = g_src[e];
        }
    }
}

// ---------------- GEMM2 standalone ------------------------------------------
__global__ __launch_bounds__(256) void gemm2_kernel(
    const float* __restrict__ as2, const float* __restrict__ ad2)
{
    extern __shared__ char dsm[];
    gemm_body<2>(blockIdx.x & 3, blockIdx.x >> 2, dsm, as2, ad2);
}

// ---------------- warp-per-node softmax + aggregate (fp16 gather) ----------
__device__ __forceinline__ void acc_edge(float4 acc[4], const float* wj,
                                         const uint2* __restrict__ hp) {
    #pragma unroll
    for (int i = 0; i < 4; i++) {
        float wgt = wj[i];
        uint2 u = hp[i * 32];
        float2 v01 = __half22float2(*(__half2*)&u.x);
        float2 v23 = __half22float2(*(__half2*)&u.y);
        acc[i].x = fmaf(wgt, v01.x, acc[i].x);
        acc[i].y = fmaf(wgt, v01.y, acc[i].y);
        acc[i].z = fmaf(wgt, v23.x, acc[i].z);
        acc[i].w = fmaf(wgt, v23.y, acc[i].w);
    }
}

template<int LAYER>
__global__ __launch_bounds__(256) void wagg_kernel(
    const float* __restrict__ bias, const float* __restrict__ W3,
    const float* __restrict__ as3p, const float* __restrict__ ad3p)
{
    __shared__ float lbuf[8][64 * 4];   // per warp: 64 edges x 4 heads
    __shared__ int   sbuf[8][64];       // per warp: src ids

    const float* __restrict__ asrc_in = (LAYER == 1) ? g_asrc : g_asrc2;
    const float* __restrict__ adst_in = (LAYER == 1) ? g_adst : g_adst2;

    int w = threadIdx.x >> 5, lane = threadIdx.x & 31;
    int n = blockIdx.x * 8 + w;
    if (n >= NN) return;
    int start = g_rowoff[n];
    int deg   = g_rowoff[n + 1] - start;
    int head  = lane & 3, eslot = lane >> 2;
    float ad = adst_in[n * 4 + head];

    float ssum;
    float4 acc[4];
    #pragma unroll
    for (int i = 0; i < 4; i++) acc[i] = make_float4(0.f, 0.f, 0.f, 0.f);

    if (deg <= 64) {
        float mx = -1e30f;
        for (int e = eslot; e < deg; e += 8) {
            int s = g_csrc[start + e];
            if (head == 0) sbuf[w][e] = s;
            float lg = leaky(asrc_in[s * 4 + head] + ad);
            lbuf[w][e * 4 + head] = lg;
            mx = fmaxf(mx, lg);
        }
        #pragma unroll
        for (int o = 4; o < 32; o <<= 1)
            mx = fmaxf(mx, __shfl_xor_sync(0xffffffffu, mx, o));
        float ls = 0.f;
        for (int e = eslot; e < deg; e += 8) {
            float wgt = __expf(lbuf[w][e * 4 + head] - mx);
            lbuf[w][e * 4 + head] = wgt;
            ls += wgt;
        }
        #pragma unroll
        for (int o = 4; o < 32; o <<= 1)
            ls += __shfl_xor_sync(0xffffffffu, ls, o);
        ssum = ls;
        __syncwarp();
        #pragma unroll 4
        for (int e2 = 0; e2 < deg; e2++) {
            const uint2* hp = (const uint2*)(g_hA + (size_t)sbuf[w][e2] * 512) + lane;
            acc_edge(acc, &lbuf[w][e2 * 4], hp);
        }
    } else {
        float mx = -1e30f;
        for (int c = 0; c < deg; c += 8) {
            int e = c + eslot;
            if (e < deg) {
                int s = g_csrc[start + e];
                mx = fmaxf(mx, leaky(asrc_in[s * 4 + head] + ad));
            }
        }
        #pragma unroll
        for (int o = 4; o < 32; o <<= 1)
            mx = fmaxf(mx, __shfl_xor_sync(0xffffffffu, mx, o));

        float ls = 0.f;
        for (int c = 0; c < deg; c += 32) {
            #pragma unroll
            for (int sp = 0; sp < 4; sp++) {
                int el = sp * 8 + eslot;
                int e = c + el;
                float wgt = 0.f;
                if (e < deg) {
                    int s = g_csrc[start + e];
                    if (head == 0) sbuf[w][el] = s;
                    wgt = __expf(leaky(asrc_in[s * 4 + head] + ad) - mx);
                }
                lbuf[w][el * 4 + head] = wgt;
                ls += wgt;
            }
            __syncwarp();
            int cend = min(32, deg - c);
            #pragma unroll 4
            for (int e2 = 0; e2 < cend; e2++) {
                const uint2* hp = (const uint2*)(g_hA + (size_t)sbuf[w][e2] * 512) + lane;
                acc_edge(acc, &lbuf[w][e2 * 4], hp);
            }
            __syncwarp();
        }
        #pragma unroll
        for (int o = 4; o < 32; o <<= 1)
            ls += __shfl_xor_sync(0xffffffffu, ls, o);
        ssum = ls;
    }

    float inv[4];
    #pragma unroll
    for (int i = 0; i < 4; i++)
        inv[i] = 1.f / (__shfl_sync(0xffffffffu, ssum, i) + 1e-16f);

    float p = 0.f;
    #pragma unroll
    for (int i = 0; i < 4; i++) {
        float4 b4 = ((const float4*)bias)[i * 32 + lane];
        float4 o;
        o.x = acc[i].x * inv[i] + b4.x;
        o.y = acc[i].y * inv[i] + b4.y;
        o.z = acc[i].z * inv[i] + b4.z;
        o.w = acc[i].w * inv[i] + b4.w;
        o.x = o.x > 0.f ? o.x : (__expf(o.x) - 1.f);
        o.y = o.y > 0.f ? o.y : (__expf(o.y) - 1.f);
        o.z = o.z > 0.f ? o.z : (__expf(o.z) - 1.f);
        o.w = o.w > 0.f ? o.w : (__expf(o.w) - 1.f);
        if (LAYER == 1) {
            __half2 h0 = __floats2half2_rn(o.x, o.y);
            __half2 h1 = __floats2half2_rn(o.z, o.w);
            size_t go = (size_t)n * 512 + i * 128 + lane * 4;
            *(uint2*)&g_hB[go] = make_uint2(*(unsigned*)&h0, *(unsigned*)&h1);
        } else {
            float4 w4 = ((const float4*)W3)[i * 32 + lane];
            p += o.x * w4.x + o.y * w4.y + o.z * w4.z + o.w * w4.w;
        }
    }
    if (LAYER == 2) {
        p = warp_red_sum(p);
        if (lane == 0) {
            g_h3[n] = p;
            g_as3[n] = p * as3p[0];
            g_ad3[n] = p * ad3p[0];
        }
    }
}

// ---------------- layer-3 aggregation ---------------------------------------
__global__ __launch_bounds__(256) void agg3_kernel(
    const float* __restrict__ b3, float* __restrict__ out)
{
    int n = blockIdx.x * 8 + (threadIdx.x >> 5);
    if (n >= NN) return;
    int lane = threadIdx.x & 31;
    int start = g_rowoff[n], deg = g_rowoff[n + 1] - start;
    float ad = g_ad3[n];
    float m = -1e30f;
    for (int e = lane; e < deg; e += 32) {
        int s = g_csrc[start + e];
        m = fmaxf(m, leaky(g_as3[s] + ad));
    }
    m = warp_red_max(m);
    float sum = 0.f, acc = 0.f;
    for (int e = lane; e < deg; e += 32) {
        int s = g_csrc[start + e];
        float w = __expf(leaky(g_as3[s] + ad) - m);
        sum += w;
        acc = fmaf(w, g_h3[s], acc);
    }
    sum = warp_red_sum(sum);
    acc = warp_red_sum(acc);
    if (!lane) out[n] = acc / (sum + 1e-16f) + b3[0];
}

// ---------------- launch ----------------------------------------------------
extern "C" void kernel_launch(void* const* d_in, const int* in_sizes, int n_in,
                              void* d_out, int out_size)
{
    const float* x   = (const float*)d_in[0];
    const void*  ei  = d_in[1];
    const float* W1  = (const float*)d_in[2];
    const float* as1 = (const float*)d_in[3];
    const float* ad1 = (const float*)d_in[4];
    const float* b1  = (const float*)d_in[5];
    const float* W2  = (const float*)d_in[6];
    const float* as2 = (const float*)d_in[7];
    const float* ad2 = (const float*)d_in[8];
    const float* b2  = (const float*)d_in[9];
    const float* W3  = (const float*)d_in[10];
    const float* as3 = (const float*)d_in[11];
    const float* ad3 = (const float*)d_in[12];
    const float* b3  = (const float*)d_in[13];
    float* out = (float*)d_out;

    cudaFuncSetAttribute(gemm1_scatter_kernel,
                         cudaFuncAttributeMaxDynamicSharedMemorySize, SM_TOTAL);
    cudaFuncSetAttribute(gemm2_kernel,
                         cudaFuncAttributeMaxDynamicSharedMemorySize, SM_TOTAL);

    int prep_blocks = DB + 256 + (NN * K1) / 256 + (FOUT * K1 + 255) / 256;

    // 0: init (dtype detect + zero + sync state)
    init_kernel<<<(NN * HEADS + 255) / 256, 256>>>((const unsigned*)ei);
    // 1: decode+count | weight/x prep
    decode_prep_kernel<<<prep_blocks, 256>>>(ei, W1, W2, x);
    // 2: fused degree scan
    scan_kernel<<<NB, 1024>>>();
    // 3: GEMM1 (+dots) overlapped with CSR scatter
    gemm1_scatter_kernel<<<G1B + DB, 256, SM_TOTAL>>>(as1, ad1);
    // 4: layer-1 softmax-aggregate
    wagg_kernel<1><<<(NN + 7) / 8, 256>>>(b1, W3, as3, ad3);
    // 5: GEMM2 (+dots)
    gemm2_kernel<<<G1B, 256, SM_TOTAL>>>(as2, ad2);
    // 6: layer-2 softmax-aggregate + fused W3 GEMV
    wagg_kernel<2><<<(NN + 7) / 8, 256>>>(b2, W3, as3, ad3);
    // 7: layer-3 scalar attention
    agg3_kernel<<<(NN + 7) / 8, 256>>>(b3, out);
}